// round 2
// baseline (speedup 1.0000x reference)
#include <cuda_runtime.h>
#include <math.h>

// ---------------------------------------------------------------------------
// CRF-as-RNN forward, restructured:
//  - spatial Gaussian filter: exact separable 1D passes (G * S * G^T)
//  - bilateral filter: exact low-rank factorization
//      K_ij = a_i a_j exp(f_i . f_j),  a = exp(-||f||^2/2), centered features
//      exp(f.g) ~= sum_m phi_m(f) phi_m(g), degree-6 Taylor, R=462 monomials
//    truncation error ~2e-8 (|f.g| <= 0.26)
// ---------------------------------------------------------------------------

static constexpr int HW   = 96;
static constexpr int NPIX = HW * HW;        // 9216
static constexpr int NC   = 21;
static constexpr int RD   = 462;            // C(11,5) monomials, degree <= 6
static constexpr int PDEG = 6;
static constexpr int MB   = 96;             // moments n-split blocks (9216/96)

// ------------------------- device scratch (no mallocs) ---------------------
__device__ float g_u[NC * NPIX];            // unaries
__device__ float g_s[NC * NPIX];            // current softmax probs
__device__ float g_tmp[NC * NPIX];          // spatial pass-X temp
__device__ float g_sp[NC * NPIX];           // spatial filtered (normalized)
__device__ float g_G[HW * HW];              // 1D Gaussian matrix
__device__ float g_gsum[HW];                // row sums of G
__device__ float g_phi[(size_t)NPIX * RD];  // a_n * phi_n[r]  (17 MB)
__device__ float g_M0[RD];                  // sum_n phi'[n][r]
__device__ float g_normbl[NPIX];            // bilateral normalizer
__device__ float g_part[MB * NC * RD];      // moments partials
__device__ float g_mom[NC * RD];            // reduced moments  [c][r]
__device__ float g_W1[NC * NC];             // comp_w @ sp_w
__device__ float g_W2[NC * NC];             // comp_w @ bl_w
__device__ float g_cvec[NC];                // folded biases

// ------------------------------ kernels ------------------------------------

__global__ void k_zero_m0() {
    int i = threadIdx.x;
    if (i < RD) g_M0[i] = 0.0f;
}

// Gaussian matrix G[i][j] = exp(-((i-j)/3)^2 / 2) and its row sums.
__global__ void k_G() {
    __shared__ float sr[HW];
    int i = blockIdx.x, j = threadIdx.x;
    float d = (float)(i - j) / 3.0f;
    float g = expf(-0.5f * d * d);
    g_G[i * HW + j] = g;
    sr[j] = g;
    __syncthreads();
    if (j == 0) {
        float t = 0.0f;
        for (int k = 0; k < HW; k++) t += sr[k];
        g_gsum[i] = t;
    }
}

// 3x3 SAME conv (cross-correlation), NCHW/OIHW.
__global__ void k_unary(const float* __restrict__ img,
                        const float* __restrict__ w,
                        const float* __restrict__ b) {
    int idx = blockIdx.x * blockDim.x + threadIdx.x;
    if (idx >= NC * NPIX) return;
    int o = idx / NPIX, n = idx % NPIX;
    int y = n / HW, x = n % HW;
    float acc = b[o];
    #pragma unroll
    for (int c = 0; c < 3; c++)
        #pragma unroll
        for (int ky = 0; ky < 3; ky++) {
            int yy = y + ky - 1;
            if (yy < 0 || yy >= HW) continue;
            #pragma unroll
            for (int kx = 0; kx < 3; kx++) {
                int xx = x + kx - 1;
                if (xx < 0 || xx >= HW) continue;
                acc += img[c * NPIX + yy * HW + xx] * w[((o * 3 + c) * 3 + ky) * 3 + kx];
            }
        }
    g_u[o * NPIX + n] = acc;
}

// Per-pixel polynomial feature row: phi'[n][r] = a_n * f^m / sqrt(prod m_j!)
__global__ void k_phi(const float* __restrict__ img) {
    int n = blockIdx.x * blockDim.x + threadIdx.x;
    if (n >= NPIX) return;
    int y = n / HW, x = n % HW;
    float f0 = ((float)x - 47.5f) * (1.0f / 160.0f);
    float f1 = ((float)y - 47.5f) * (1.0f / 160.0f);
    float f2 = (img[0 * NPIX + n] - 0.5f) * (1.0f / 3.0f);
    float f3 = (img[1 * NPIX + n] - 0.5f) * (1.0f / 3.0f);
    float f4 = (img[2 * NPIX + n] - 0.5f) * (1.0f / 3.0f);
    float a = expf(-0.5f * (f0 * f0 + f1 * f1 + f2 * f2 + f3 * f3 + f4 * f4));

    float pw0[PDEG + 1], pw1[PDEG + 1], pw2[PDEG + 1], pw3[PDEG + 1], pw4[PDEG + 1];
    pw0[0] = pw1[0] = pw2[0] = pw3[0] = pw4[0] = 1.0f;
    for (int k = 1; k <= PDEG; k++) {
        pw0[k] = pw0[k - 1] * f0;
        pw1[k] = pw1[k - 1] * f1;
        pw2[k] = pw2[k - 1] * f2;
        pw3[k] = pw3[k - 1] * f3;
        pw4[k] = pw4[k - 1] * f4;
    }
    // 1/sqrt(k!) for k=0..6
    const float rs[PDEG + 1] = {1.0f, 1.0f, 0.70710678f, 0.40824829f,
                                0.20412415f, 0.091287093f, 0.037267799f};
    float* out = g_phi + (size_t)n * RD;
    int r = 0;
    for (int m0 = 0; m0 <= PDEG; m0++) {
        float v0 = a * pw0[m0] * rs[m0];
        for (int m1 = 0; m1 <= PDEG - m0; m1++) {
            float v1 = v0 * pw1[m1] * rs[m1];
            for (int m2 = 0; m2 <= PDEG - m0 - m1; m2++) {
                float v2 = v1 * pw2[m2] * rs[m2];
                for (int m3 = 0; m3 <= PDEG - m0 - m1 - m2; m3++) {
                    float v3 = v2 * pw3[m3] * rs[m3];
                    for (int m4 = 0; m4 <= PDEG - m0 - m1 - m2 - m3; m4++) {
                        out[r++] = v3 * pw4[m4] * rs[m4];
                    }
                }
            }
        }
    }
}

// M0[r] = sum_n phi'[n][r]
__global__ void k_M0() {
    int r = threadIdx.x;
    int b = blockIdx.x;
    if (r >= RD) return;
    int n0 = b * (NPIX / MB);
    float acc = 0.0f;
    for (int i = 0; i < NPIX / MB; i++)
        acc += g_phi[(size_t)(n0 + i) * RD + r];
    atomicAdd(&g_M0[r], acc);
}

// norm_bl[n] = phi'[n] . M0   (warp per pixel)
__global__ void k_normbl() {
    __shared__ float sM0[RD];
    for (int i = threadIdx.x; i < RD; i += blockDim.x) sM0[i] = g_M0[i];
    __syncthreads();
    int lane = threadIdx.x & 31;
    int nwarps = gridDim.x * (blockDim.x >> 5);
    int gw = blockIdx.x * (blockDim.x >> 5) + (threadIdx.x >> 5);
    for (int n = gw; n < NPIX; n += nwarps) {
        const float* ph = g_phi + (size_t)n * RD;
        float acc = 0.0f;
        for (int r = lane; r < RD; r += 32) acc += ph[r] * sM0[r];
        #pragma unroll
        for (int o = 16; o > 0; o >>= 1) acc += __shfl_xor_sync(0xffffffffu, acc, o);
        if (lane == 0) g_normbl[n] = acc;
    }
}

// W1 = comp_w @ sp_w, W2 = comp_w @ bl_w, cvec = comp_w@(sp_b+bl_b)+comp_b
__global__ void k_W(const float* __restrict__ sp_w, const float* __restrict__ sp_b,
                    const float* __restrict__ bl_w, const float* __restrict__ bl_b,
                    const float* __restrict__ comp_w, const float* __restrict__ comp_b) {
    int idx = threadIdx.x;
    if (idx < NC * NC) {
        int o = idx / NC, k = idx % NC;
        float a1 = 0.0f, a2 = 0.0f;
        for (int c = 0; c < NC; c++) {
            a1 += comp_w[o * NC + c] * sp_w[c * NC + k];
            a2 += comp_w[o * NC + c] * bl_w[c * NC + k];
        }
        g_W1[idx] = a1;
        g_W2[idx] = a2;
    }
    if (idx < NC) {
        float cv = comp_b[idx];
        for (int c = 0; c < NC; c++)
            cv += comp_w[idx * NC + c] * (sp_b[c] + bl_b[c]);
        g_cvec[idx] = cv;
    }
}

// initial s = softmax(u) over classes. Warp per pixel, lane=class.
__global__ void k_init() {
    int lane = threadIdx.x & 31;
    int nwarps = gridDim.x * (blockDim.x >> 5);
    int gw = blockIdx.x * (blockDim.x >> 5) + (threadIdx.x >> 5);
    for (int n = gw; n < NPIX; n += nwarps) {
        float q = (lane < NC) ? g_u[lane * NPIX + n] : -1e30f;
        float m = q;
        #pragma unroll
        for (int o = 16; o > 0; o >>= 1) m = fmaxf(m, __shfl_xor_sync(0xffffffffu, m, o));
        float e = (lane < NC) ? expf(q - m) : 0.0f;
        float ss = e;
        #pragma unroll
        for (int o = 16; o > 0; o >>= 1) ss += __shfl_xor_sync(0xffffffffu, ss, o);
        if (lane < NC) g_s[lane * NPIX + n] = e / ss;
    }
}

// moments partials: part[b][c][r] = sum_{n in chunk b} phi'[n][r] * s[c][n]
__global__ void __launch_bounds__(480) k_moments() {
    __shared__ float ss[NC][NPIX / MB];     // 21 x 96 tile of s
    int b = blockIdx.x;
    int n0 = b * (NPIX / MB);
    for (int idx = threadIdx.x; idx < NC * (NPIX / MB); idx += blockDim.x) {
        int c = idx / (NPIX / MB), i = idx % (NPIX / MB);
        ss[c][i] = g_s[c * NPIX + n0 + i];
    }
    __syncthreads();
    int r = threadIdx.x;
    if (r >= RD) return;
    float acc[NC];
    #pragma unroll
    for (int c = 0; c < NC; c++) acc[c] = 0.0f;
    for (int i = 0; i < NPIX / MB; i++) {
        float p = g_phi[(size_t)(n0 + i) * RD + r];
        #pragma unroll
        for (int c = 0; c < NC; c++) acc[c] += p * ss[c][i];
    }
    #pragma unroll
    for (int c = 0; c < NC; c++)
        g_part[(size_t)b * NC * RD + c * RD + r] = acc[c];
}

// reduce partials -> g_mom[c*RD+r]
__global__ void k_momreduce() {
    int j = blockIdx.x * blockDim.x + threadIdx.x;
    if (j >= NC * RD) return;
    float acc = 0.0f;
    for (int b = 0; b < MB; b++) acc += g_part[(size_t)b * NC * RD + j];
    g_mom[j] = acc;
}

// spatial pass X: tmp[c][y][x] = sum_x' G[x'][x] * s[c][y][x']
__global__ void k_spX() {
    __shared__ float row[HW];
    int c = blockIdx.x / HW, y = blockIdx.x % HW;
    int x = threadIdx.x;
    row[x] = g_s[c * NPIX + y * HW + x];
    __syncthreads();
    float acc = 0.0f;
    for (int xp = 0; xp < HW; xp++)
        acc += g_G[xp * HW + x] * row[xp];   // G symmetric; coalesced in x
    g_tmp[c * NPIX + y * HW + x] = acc;
}

// spatial pass Y + normalize: sp[c][y][x] = (sum_y' G[y][y'] tmp[c][y'][x]) / (gsum[y]*gsum[x])
__global__ void k_spY() {
    int c = blockIdx.x / HW, y = blockIdx.x % HW;
    int x = threadIdx.x;
    float acc = 0.0f;
    for (int yp = 0; yp < HW; yp++)
        acc += g_G[y * HW + yp] * g_tmp[c * NPIX + yp * HW + x];
    g_sp[c * NPIX + y * HW + x] = acc / (g_gsum[y] * g_gsum[x]);
}

// fused: bilateral back-projection + mixing + q = u - pairwise + softmax
__global__ void __launch_bounds__(256) k_update(float* __restrict__ out, int write_out) {
    __shared__ float sM[NC * RD];           // 38808 B
    __shared__ float sW1[NC * NC], sW2[NC * NC], sCv[NC];
    for (int i = threadIdx.x; i < NC * RD; i += blockDim.x) sM[i] = g_mom[i];
    for (int i = threadIdx.x; i < NC * NC; i += blockDim.x) { sW1[i] = g_W1[i]; sW2[i] = g_W2[i]; }
    if (threadIdx.x < NC) sCv[threadIdx.x] = g_cvec[threadIdx.x];
    __syncthreads();

    int lane = threadIdx.x & 31;
    int nwarps = gridDim.x * (blockDim.x >> 5);
    int gw = blockIdx.x * (blockDim.x >> 5) + (threadIdx.x >> 5);

    for (int n = gw; n < NPIX; n += nwarps) {
        float bl = 0.0f, sp = 0.0f, uu = 0.0f;
        if (lane < NC) {
            const float* __restrict__ ph = g_phi + (size_t)n * RD;
            const float* __restrict__ mr = sM + lane * RD;
            float acc = 0.0f;
            #pragma unroll 6
            for (int r = 0; r < RD; r++) acc += ph[r] * mr[r];
            bl = acc / g_normbl[n];
            sp = g_sp[lane * NPIX + n];
            uu = g_u[lane * NPIX + n];
        }
        float pair = (lane < NC) ? sCv[lane] : 0.0f;
        #pragma unroll
        for (int cp = 0; cp < NC; cp++) {
            float spv = __shfl_sync(0xffffffffu, sp, cp);
            float blv = __shfl_sync(0xffffffffu, bl, cp);
            if (lane < NC) pair += sW1[lane * NC + cp] * spv + sW2[lane * NC + cp] * blv;
        }
        float q = (lane < NC) ? (uu - pair) : -1e30f;
        float m = q;
        #pragma unroll
        for (int o = 16; o > 0; o >>= 1) m = fmaxf(m, __shfl_xor_sync(0xffffffffu, m, o));
        float e = (lane < NC) ? expf(q - m) : 0.0f;
        float ssum = e;
        #pragma unroll
        for (int o = 16; o > 0; o >>= 1) ssum += __shfl_xor_sync(0xffffffffu, ssum, o);
        float sv = e / ssum;
        if (lane < NC) {
            g_s[lane * NPIX + n] = sv;
            if (write_out) out[lane * NPIX + n] = sv;
        }
    }
}

// ------------------------------ launch -------------------------------------
extern "C" void kernel_launch(void* const* d_in, const int* in_sizes, int n_in,
                              void* d_out, int out_size) {
    const float* image  = (const float*)d_in[0];
    const float* net_w  = (const float*)d_in[1];
    const float* net_b  = (const float*)d_in[2];
    const float* sp_w   = (const float*)d_in[3];
    const float* sp_b   = (const float*)d_in[4];
    const float* bl_w   = (const float*)d_in[5];
    const float* bl_b   = (const float*)d_in[6];
    const float* comp_w = (const float*)d_in[7];
    const float* comp_b = (const float*)d_in[8];
    float* out = (float*)d_out;

    // ---- precompute ----
    k_zero_m0<<<1, RD>>>();
    k_G<<<HW, HW>>>();
    k_unary<<<(NC * NPIX + 255) / 256, 256>>>(image, net_w, net_b);
    k_phi<<<(NPIX + 127) / 128, 128>>>(image);
    k_W<<<1, 512>>>(sp_w, sp_b, bl_w, bl_b, comp_w, comp_b);
    k_M0<<<MB, 480>>>();
    k_normbl<<<148, 256>>>();
    k_init<<<148, 256>>>();

    // ---- mean-field iterations ----
    for (int it = 0; it < 5; it++) {
        k_moments<<<MB, 480>>>();
        k_momreduce<<<(NC * RD + 255) / 256, 256>>>();
        k_spX<<<NC * HW, HW>>>();
        k_spY<<<NC * HW, HW>>>();
        k_update<<<296, 256>>>(out, it == 4 ? 1 : 0);
    }
}

// round 3
// speedup vs baseline: 1.4220x; 1.4220x over previous
#include <cuda_runtime.h>
#include <math.h>

// ---------------------------------------------------------------------------
// CRF-as-RNN forward.
//  - spatial Gaussian filter: exact separable 1D passes, pre-normalized
//  - bilateral filter: low-rank feature map, degree-5 Taylor, R=252 monomials
//      K_ij = a_i a_j exp(f_i . f_j), truncation err ~6e-7 (|f.g| <= 0.26)
//  - phiT[r][n] layout: every hot load/store coalesced along n
//  - backprojection uses packed fma.rn.f32x2 (2 pixels per lane-op)
// ---------------------------------------------------------------------------

static constexpr int HW   = 96;
static constexpr int NPIX = HW * HW;     // 9216
static constexpr int NC   = 21;
static constexpr int RD   = 252;         // monomials of degree <= 5 in 5 vars
static constexpr int RSPLIT = 4;
static constexpr int RCH  = RD / RSPLIT; // 63

// ------------------------- device scratch ----------------------------------
__device__ float g_u[NC * NPIX];
__device__ float g_s[NC * NPIX];
__device__ float g_tmp[NC * NPIX];
__device__ float g_sp[NC * NPIX];
__device__ float g_Gn[HW * HW];          // row-normalized 1D Gaussian
__device__ float g_GnT[HW * HW];         // its transpose
__device__ float g_phiT[(size_t)RD * NPIX];  // 9.3 MB, [r][n]
__device__ float g_M0[RD];
__device__ float g_normbl[NPIX];
__device__ float g_part[RSPLIT * NC * NPIX]; // backproj partials
__device__ float g_mom[NC * RD];
__device__ float g_W1[NC * NC];
__device__ float g_W2[NC * NC];
__device__ float g_cvec[NC];
__device__ unsigned int g_monoE[RD];     // packed exponents (3 bits each)
__device__ float g_monoC[RD];            // 1/sqrt(prod m_j!)

// ------------------------------ setup kernels ------------------------------

// Enumerate monomials (degree <= 5 over 5 vars), fixed order.
__global__ void k_mono() {
    const float rs[6] = {1.0f, 1.0f, 0.70710678f, 0.40824829f,
                         0.20412415f, 0.091287093f};
    int r = 0;
    for (int m0 = 0; m0 <= 5; m0++)
        for (int m1 = 0; m1 <= 5 - m0; m1++)
            for (int m2 = 0; m2 <= 5 - m0 - m1; m2++)
                for (int m3 = 0; m3 <= 5 - m0 - m1 - m2; m3++)
                    for (int m4 = 0; m4 <= 5 - m0 - m1 - m2 - m3; m4++) {
                        g_monoE[r] = (unsigned)(m0 | (m1 << 3) | (m2 << 6) |
                                                (m3 << 9) | (m4 << 12));
                        g_monoC[r] = rs[m0] * rs[m1] * rs[m2] * rs[m3] * rs[m4];
                        r++;
                    }
}

// Row-normalized 1D Gaussian + transpose.
__global__ void k_G() {
    __shared__ float sr[HW];
    int i = blockIdx.x, j = threadIdx.x;
    float d = (float)(i - j) * (1.0f / 3.0f);
    float g = expf(-0.5f * d * d);
    sr[j] = g;
    __syncthreads();
    float t = 0.0f;
    for (int k = 0; k < HW; k++) t += sr[k];
    float gn = g / t;
    g_Gn[i * HW + j] = gn;
    g_GnT[j * HW + i] = gn;
}

// Folded mixing matrices + zero g_mom for first iteration.
__global__ void k_W(const float* __restrict__ sp_w, const float* __restrict__ sp_b,
                    const float* __restrict__ bl_w, const float* __restrict__ bl_b,
                    const float* __restrict__ comp_w, const float* __restrict__ comp_b) {
    int idx = threadIdx.x;
    if (idx < NC * NC) {
        int o = idx / NC, k = idx % NC;
        float a1 = 0.0f, a2 = 0.0f;
        for (int c = 0; c < NC; c++) {
            a1 += comp_w[o * NC + c] * sp_w[c * NC + k];
            a2 += comp_w[o * NC + c] * bl_w[c * NC + k];
        }
        g_W1[idx] = a1;
        g_W2[idx] = a2;
    }
    if (idx < NC) {
        float cv = comp_b[idx];
        for (int c = 0; c < NC; c++)
            cv += comp_w[idx * NC + c] * (sp_b[c] + bl_b[c]);
        g_cvec[idx] = cv;
    }
    for (int i = idx; i < NC * RD; i += blockDim.x) g_mom[i] = 0.0f;
}

// 3x3 SAME conv (cross-correlation), NCHW/OIHW.
__global__ void k_unary(const float* __restrict__ img,
                        const float* __restrict__ w,
                        const float* __restrict__ b) {
    int idx = blockIdx.x * blockDim.x + threadIdx.x;
    if (idx >= NC * NPIX) return;
    int o = idx / NPIX, n = idx % NPIX;
    int y = n / HW, x = n % HW;
    float acc = b[o];
    #pragma unroll
    for (int c = 0; c < 3; c++)
        #pragma unroll
        for (int ky = 0; ky < 3; ky++) {
            int yy = y + ky - 1;
            if (yy < 0 || yy >= HW) continue;
            #pragma unroll
            for (int kx = 0; kx < 3; kx++) {
                int xx = x + kx - 1;
                if (xx < 0 || xx >= HW) continue;
                acc += img[c * NPIX + yy * HW + xx] * w[((o * 3 + c) * 3 + ky) * 3 + kx];
            }
        }
    g_u[o * NPIX + n] = acc;
}

// phiT[r][n] = a_n * coeff_r * prod f^m  — coalesced stores along n.
__global__ __launch_bounds__(128) void k_phiT(const float* __restrict__ img) {
    __shared__ float spw[5 * 6 * 128];     // [(v*6+k)][tid]
    int tid = threadIdx.x;
    int n = blockIdx.x * 128 + tid;
    int y = n / HW, x = n % HW;
    float f[5];
    f[0] = ((float)x - 47.5f) * (1.0f / 160.0f);
    f[1] = ((float)y - 47.5f) * (1.0f / 160.0f);
    f[2] = (img[0 * NPIX + n] - 0.5f) * (1.0f / 3.0f);
    f[3] = (img[1 * NPIX + n] - 0.5f) * (1.0f / 3.0f);
    f[4] = (img[2 * NPIX + n] - 0.5f) * (1.0f / 3.0f);
    float a = expf(-0.5f * (f[0]*f[0] + f[1]*f[1] + f[2]*f[2] + f[3]*f[3] + f[4]*f[4]));
    #pragma unroll
    for (int v = 0; v < 5; v++) {
        float p = (v == 0) ? a : 1.0f;     // fold 'a' into var-0 powers
        #pragma unroll
        for (int k = 0; k <= 5; k++) {
            spw[(v * 6 + k) * 128 + tid] = p;
            p *= f[v];
        }
    }
    // no __syncthreads needed: each thread reads only its own column
    int rbase = blockIdx.y * RCH;
    for (int jj = 0; jj < RCH; jj++) {
        int r = rbase + jj;
        unsigned e = g_monoE[r];
        float val = g_monoC[r];
        val *= spw[((e        & 7))       * 128 + tid];
        val *= spw[(6  + ((e >> 3)  & 7)) * 128 + tid];
        val *= spw[(12 + ((e >> 6)  & 7)) * 128 + tid];
        val *= spw[(18 + ((e >> 9)  & 7)) * 128 + tid];
        val *= spw[(24 + ((e >> 12) & 7)) * 128 + tid];
        g_phiT[(size_t)r * NPIX + n] = val;
    }
}

// M0[r] = sum_n phiT[r][n]
__global__ void k_M0() {
    __shared__ float red[256];
    int r = blockIdx.x, tid = threadIdx.x;
    const float* row = g_phiT + (size_t)r * NPIX;
    float acc = 0.0f;
    for (int i = tid; i < NPIX; i += 256) acc += row[i];
    red[tid] = acc;
    __syncthreads();
    for (int s = 128; s > 0; s >>= 1) {
        if (tid < s) red[tid] += red[tid + s];
        __syncthreads();
    }
    if (tid == 0) g_M0[r] = red[0];
}

// norm_bl[n] = phiT[:, n] . M0
__global__ __launch_bounds__(256) void k_normbl() {
    __shared__ float sM0[RD];
    for (int i = threadIdx.x; i < RD; i += 256) sM0[i] = g_M0[i];
    __syncthreads();
    int n = blockIdx.x * 256 + threadIdx.x;
    float acc = 0.0f;
    for (int r = 0; r < RD; r++)
        acc += g_phiT[(size_t)r * NPIX + n] * sM0[r];
    g_normbl[n] = acc;
}

// initial s = softmax(u). Warp per pixel, lane = class.
__global__ __launch_bounds__(256) void k_init() {
    int lane = threadIdx.x & 31;
    int nwarps = gridDim.x * 8;
    int gw = blockIdx.x * 8 + (threadIdx.x >> 5);
    for (int n = gw; n < NPIX; n += nwarps) {
        float q = (lane < NC) ? g_u[lane * NPIX + n] : -1e30f;
        float m = q;
        #pragma unroll
        for (int o = 16; o > 0; o >>= 1) m = fmaxf(m, __shfl_xor_sync(0xffffffffu, m, o));
        float e = (lane < NC) ? expf(q - m) : 0.0f;
        float ss = e;
        #pragma unroll
        for (int o = 16; o > 0; o >>= 1) ss += __shfl_xor_sync(0xffffffffu, ss, o);
        if (lane < NC) g_s[lane * NPIX + n] = e / ss;
    }
}

// --------------------------- per-iteration kernels -------------------------

// moments: g_mom[c][r] += sum_n phiT[r][n] * s[c][n].  4-r register blocking.
__global__ __launch_bounds__(256) void k_moments() {
    __shared__ float sS[NC][384];
    int ns = blockIdx.x;                  // 0..23 (n tile)
    int rb = blockIdx.y;                  // 0..7  (32-r tile)
    int n0 = ns * 384;
    int tid = threadIdx.x;
    for (int idx = tid; idx < NC * 384; idx += 256) {
        int c = idx / 384, i = idx % 384;
        sS[c][i] = g_s[c * NPIX + n0 + i];
    }
    __syncthreads();
    int w = tid >> 5, lane = tid & 31;
    int r0 = rb * 32 + w * 4;
    if (r0 >= RD) return;                 // only (rb=7, w=7) idles
    float acc[4][NC];
    #pragma unroll
    for (int k = 0; k < 4; k++)
        #pragma unroll
        for (int c = 0; c < NC; c++) acc[k][c] = 0.0f;
    for (int i = 0; i < 12; i++) {
        int nn = i * 32 + lane;
        float p0 = g_phiT[(size_t)(r0 + 0) * NPIX + n0 + nn];
        float p1 = g_phiT[(size_t)(r0 + 1) * NPIX + n0 + nn];
        float p2 = g_phiT[(size_t)(r0 + 2) * NPIX + n0 + nn];
        float p3 = g_phiT[(size_t)(r0 + 3) * NPIX + n0 + nn];
        #pragma unroll
        for (int c = 0; c < NC; c++) {
            float sv = sS[c][nn];
            acc[0][c] += p0 * sv;
            acc[1][c] += p1 * sv;
            acc[2][c] += p2 * sv;
            acc[3][c] += p3 * sv;
        }
    }
    #pragma unroll
    for (int k = 0; k < 4; k++)
        #pragma unroll
        for (int c = 0; c < NC; c++) {
            float v = acc[k][c];
            #pragma unroll
            for (int o = 16; o > 0; o >>= 1) v += __shfl_xor_sync(0xffffffffu, v, o);
            if (lane == 0) atomicAdd(&g_mom[c * RD + r0 + k], v);
        }
}

// spatial pass X: tmp[c][y][x] = sum_xp GnT[xp][x] * s[c][y][xp]
__global__ void k_spX() {
    __shared__ float row[HW];
    int c = blockIdx.x / HW, y = blockIdx.x % HW;
    int x = threadIdx.x;
    row[x] = g_s[c * NPIX + y * HW + x];
    __syncthreads();
    float acc = 0.0f;
    for (int xp = 0; xp < HW; xp++)
        acc += g_GnT[xp * HW + x] * row[xp];
    g_tmp[c * NPIX + y * HW + x] = acc;
}

// spatial pass Y: sp[c][y][x] = sum_yp Gn[y][yp] * tmp[c][yp][x]
__global__ void k_spY() {
    __shared__ float gr[HW];
    int c = blockIdx.x / HW, y = blockIdx.x % HW;
    int x = threadIdx.x;
    gr[x] = g_Gn[y * HW + x];
    __syncthreads();
    float acc = 0.0f;
    for (int yp = 0; yp < HW; yp++)
        acc += gr[yp] * g_tmp[c * NPIX + yp * HW + x];
    g_sp[c * NPIX + y * HW + x] = acc;
}

// bilateral backprojection partials: part[s][c][n] = phiT[rchunk,:n].M[c][rchunk]
// Packed f32x2 FMA: each thread owns 2 adjacent pixels, 21 packed accumulators.
__global__ __launch_bounds__(128) void k_bl() {
    __shared__ unsigned long long sM2[NC * RCH];   // duplicated M values
    int tid = threadIdx.x;
    int rsp = blockIdx.y;
    int rb = rsp * RCH;
    for (int idx = tid; idx < NC * RCH; idx += 128) {
        int c = idx / RCH, j = idx % RCH;
        unsigned int ui = __float_as_uint(g_mom[c * RD + rb + j]);
        sM2[idx] = ((unsigned long long)ui << 32) | (unsigned long long)ui;
    }
    __syncthreads();
    int n2 = blockIdx.x * 128 + tid;               // float2 pixel-pair index
    unsigned long long acc[NC];
    #pragma unroll
    for (int c = 0; c < NC; c++) acc[c] = 0ull;
    for (int j = 0; j < RCH; j++) {
        const unsigned long long* rowp =
            reinterpret_cast<const unsigned long long*>(g_phiT + (size_t)(rb + j) * NPIX);
        unsigned long long p = rowp[n2];
        #pragma unroll
        for (int c = 0; c < NC; c++) {
            asm("fma.rn.f32x2 %0, %1, %2, %0;"
                : "+l"(acc[c]) : "l"(p), "l"(sM2[c * RCH + j]));
        }
    }
    #pragma unroll
    for (int c = 0; c < NC; c++) {
        float2 v;
        v.x = __uint_as_float((unsigned int)(acc[c] & 0xffffffffull));
        v.y = __uint_as_float((unsigned int)(acc[c] >> 32));
        reinterpret_cast<float2*>(g_part + (size_t)(rsp * NC + c) * NPIX)[n2] = v;
    }
}

// combine partials + normalize + mixing + softmax; zero g_mom for next iter.
__global__ __launch_bounds__(256) void k_post(float* __restrict__ out, int write_out) {
    __shared__ float sW1[NC * NC], sW2[NC * NC], sCv[NC];
    int tid = threadIdx.x;
    for (int i = tid; i < NC * NC; i += 256) { sW1[i] = g_W1[i]; sW2[i] = g_W2[i]; }
    if (tid < NC) sCv[tid] = g_cvec[tid];
    if (blockIdx.x < NC) {                  // zero g_mom slice for next moments
        for (int i = tid; i < RD; i += 256) g_mom[blockIdx.x * RD + i] = 0.0f;
    }
    __syncthreads();

    int lane = tid & 31;
    int nwarps = gridDim.x * 8;
    int gw = blockIdx.x * 8 + (tid >> 5);
    for (int n = gw; n < NPIX; n += nwarps) {
        float bl = 0.0f, sp = 0.0f, uu = 0.0f;
        if (lane < NC) {
            float num = g_part[(0 * NC + lane) * NPIX + n]
                      + g_part[(1 * NC + lane) * NPIX + n]
                      + g_part[(2 * NC + lane) * NPIX + n]
                      + g_part[(3 * NC + lane) * NPIX + n];
            bl = num / g_normbl[n];
            sp = g_sp[lane * NPIX + n];
            uu = g_u[lane * NPIX + n];
        }
        float pair = (lane < NC) ? sCv[lane] : 0.0f;
        #pragma unroll
        for (int cp = 0; cp < NC; cp++) {
            float spv = __shfl_sync(0xffffffffu, sp, cp);
            float blv = __shfl_sync(0xffffffffu, bl, cp);
            if (lane < NC) pair += sW1[lane * NC + cp] * spv + sW2[lane * NC + cp] * blv;
        }
        float q = (lane < NC) ? (uu - pair) : -1e30f;
        float m = q;
        #pragma unroll
        for (int o = 16; o > 0; o >>= 1) m = fmaxf(m, __shfl_xor_sync(0xffffffffu, m, o));
        float e = (lane < NC) ? expf(q - m) : 0.0f;
        float ssum = e;
        #pragma unroll
        for (int o = 16; o > 0; o >>= 1) ssum += __shfl_xor_sync(0xffffffffu, ssum, o);
        float sv = e / ssum;
        if (lane < NC) {
            g_s[lane * NPIX + n] = sv;
            if (write_out) out[lane * NPIX + n] = sv;
        }
    }
}

// ------------------------------ launch -------------------------------------
extern "C" void kernel_launch(void* const* d_in, const int* in_sizes, int n_in,
                              void* d_out, int out_size) {
    const float* image  = (const float*)d_in[0];
    const float* net_w  = (const float*)d_in[1];
    const float* net_b  = (const float*)d_in[2];
    const float* sp_w   = (const float*)d_in[3];
    const float* sp_b   = (const float*)d_in[4];
    const float* bl_w   = (const float*)d_in[5];
    const float* bl_b   = (const float*)d_in[6];
    const float* comp_w = (const float*)d_in[7];
    const float* comp_b = (const float*)d_in[8];
    float* out = (float*)d_out;

    // ---- setup ----
    k_mono<<<1, 1>>>();
    k_G<<<HW, HW>>>();
    k_W<<<1, 512>>>(sp_w, sp_b, bl_w, bl_b, comp_w, comp_b);
    k_unary<<<(NC * NPIX + 255) / 256, 256>>>(image, net_w, net_b);
    k_phiT<<<dim3(72, 4), 128>>>(image);
    k_M0<<<RD, 256>>>();
    k_normbl<<<36, 256>>>();
    k_init<<<96, 256>>>();

    // ---- mean-field iterations ----
    for (int it = 0; it < 5; it++) {
        k_moments<<<dim3(24, 8), 256>>>();
        k_spX<<<NC * HW, HW>>>();
        k_spY<<<NC * HW, HW>>>();
        k_bl<<<dim3(36, 4), 128>>>();
        k_post<<<96, 256>>>(out, it == 4 ? 1 : 0);
    }
}